// round 3
// baseline (speedup 1.0000x reference)
#include <cuda_runtime.h>

// PotEnergy1P: out[b] = sum_{i<12, k} exp(-r)/(r+0.01), r = |x[b,i]-nbr[i,k]|
// 2 MUFU per pair (sqrt, ex2); rcp via bit-seed + 2 Newton (FMA pipe),
// all FMA math packed f32x2. 4 threads per batch element (3 sites each) to
// raise warp count 4x and hide MUFU latency; shfl reduction at the end.

#define NSITES 12
#define NMAX   64
#define NGRP   32          // neighbor pairs per site
#define SPT    3           // sites per thread
#define TPB    4           // threads per batch element

typedef unsigned long long u64;

#define C_NEGL2E 0xBFB8AA3BBFB8AA3BULL   // -log2(e)
#define C_B      0x3C23D70A3C23D70AULL   // 0.01f
#define C_TWO    0x4000000040000000ULL   // 2.0f
#define C_SGN    0x8000000080000000ULL

__device__ __forceinline__ u64 pk2(float lo, float hi) {
    u64 r; asm("mov.b64 %0, {%1,%2};" : "=l"(r) : "f"(lo), "f"(hi)); return r;
}
__device__ __forceinline__ void upk2(float& lo, float& hi, u64 v) {
    asm("mov.b64 {%0,%1}, %2;" : "=f"(lo), "=f"(hi) : "l"(v));
}
__device__ __forceinline__ u64 addx2(u64 a, u64 b) {
    u64 d; asm("add.rn.f32x2 %0,%1,%2;" : "=l"(d) : "l"(a), "l"(b)); return d;
}
__device__ __forceinline__ u64 mulx2(u64 a, u64 b) {
    u64 d; asm("mul.rn.f32x2 %0,%1,%2;" : "=l"(d) : "l"(a), "l"(b)); return d;
}
__device__ __forceinline__ u64 fmax2(u64 a, u64 b, u64 c) {
    u64 d; asm("fma.rn.f32x2 %0,%1,%2,%3;" : "=l"(d) : "l"(a), "l"(b), "l"(c)); return d;
}
__device__ __forceinline__ float fsqrt_approx(float a) {
    float r; asm("sqrt.approx.f32 %0, %1;" : "=f"(r) : "f"(a)); return r;
}
__device__ __forceinline__ float fex2_approx(float a) {
    float r; asm("ex2.approx.f32 %0, %1;" : "=f"(r) : "f"(a)); return r;
}
__device__ __forceinline__ float rcp_seed(float a) {
    return __int_as_float(0x7EF311C3 - __float_as_int(a));
}
__device__ __forceinline__ u64 pkbits(float lo, float hi) {
    return (u64)__float_as_uint(lo) | ((u64)__float_as_uint(hi) << 32);
}

__global__ __launch_bounds__(128)
void pot_energy_kernel(const float* __restrict__ x,
                       const float* __restrict__ nbr,
                       const float* __restrict__ mask,
                       float* __restrict__ out,
                       int batch)
{
    // Geometry per 2-neighbor group, pre-negated + pre-packed:
    //   s_geo[j] = { pk(-nx0,-nx1), pk(-ny0,-ny1) }
    __shared__ ulonglong2 s_geo[NSITES * NGRP];
    __shared__ int        s_ng[NSITES];

    for (int j = threadIdx.x; j < NSITES * NGRP; j += blockDim.x) {
        int base = j * 4;
        float nx0 = nbr[base + 0], ny0 = nbr[base + 1];
        float nx1 = nbr[base + 2], ny1 = nbr[base + 3];
        ulonglong2 v;
        v.x = pkbits(-nx0, -nx1);
        v.y = pkbits(-ny0, -ny1);
        s_geo[j] = v;
    }
    if (threadIdx.x < NSITES) {
        int c = 0;
        for (int k = 0; k < NMAX; ++k)
            c += (mask[threadIdx.x * NMAX + k] > 0.5f) ? 1 : 0;
        s_ng[threadIdx.x] = (c + 1) >> 1;       // odd tail self-masks (FAR)
    }
    __syncthreads();

    int t = blockIdx.x * blockDim.x + threadIdx.x;
    int b = t >> 2;                 // batch element
    int g = t & 3;                  // site-group 0..3 -> sites 3g..3g+2
    if (b >= batch) return;

    // 6 floats: coords of sites 3g..3g+2. Warp reads a contiguous 768B span.
    const float* xp = x + (size_t)b * 24 + g * 6;
    float xs[6];
#pragma unroll
    for (int j = 0; j < 3; ++j) {
        float2 v = reinterpret_cast<const float2*>(xp)[j];
        xs[2 * j] = v.x; xs[2 * j + 1] = v.y;
    }

    u64 acc = 0ULL;

#pragma unroll
    for (int s = 0; s < SPT; ++s) {
        int site = 3 * g + s;
        u64 xip = pk2(xs[2 * s],     xs[2 * s]);
        u64 yip = pk2(xs[2 * s + 1], xs[2 * s + 1]);
        const ulonglong2* geo = s_geo + site * NGRP;
        int ng = s_ng[site];
#pragma unroll 4
        for (int k = 0; k < ng; ++k) {
            ulonglong2 q = geo[k];              // LDS.128
            u64 dx = addx2(xip, q.x);           // xi - nx (pre-negated)
            u64 dy = addx2(yip, q.y);
            u64 d2 = fmax2(dx, dx, mulx2(dy, dy));

            float d2l, d2h; upk2(d2l, d2h, d2);
            float rl = fsqrt_approx(d2l);       // MUFU
            float rh = fsqrt_approx(d2h);       // MUFU
            u64 rp = pk2(rl, rh);

            u64 w    = addx2(rp, C_B);          // r + b
            u64 targ = mulx2(rp, C_NEGL2E);
            float tl, th; upk2(tl, th, targ);
            float el = fex2_approx(tl);         // MUFU (FAR -> 0)
            float eh = fex2_approx(th);         // MUFU
            u64 e = pk2(el, eh);

            float wl, wh; upk2(wl, wh, w);
            u64 y  = pk2(rcp_seed(wl), rcp_seed(wh));
            u64 wn = w ^ C_SGN;
            u64 tt = fmax2(wn, y, C_TWO);  y = mulx2(y, tt);
            tt     = fmax2(wn, y, C_TWO);  y = mulx2(y, tt);

            acc = fmax2(e, y, acc);
        }
    }

    float al, ah; upk2(al, ah, acc);
    float v = al + ah;
    v += __shfl_xor_sync(0xffffffffu, v, 1);
    v += __shfl_xor_sync(0xffffffffu, v, 2);
    if (g == 0) out[b] = v;
}

extern "C" void kernel_launch(void* const* d_in, const int* in_sizes, int n_in,
                              void* d_out, int out_size)
{
    const float* x    = (const float*)d_in[0];   // [B, 24]
    const float* nbr  = (const float*)d_in[1];   // [12, 64, 2]
    const float* mask = (const float*)d_in[2];   // [12, 64]
    float* out        = (float*)d_out;           // [B]

    int batch = in_sizes[0] / 24;
    const int threads = 128;                     // 32 batch elems per block
    int blocks = (batch * TPB + threads - 1) / threads;
    pot_energy_kernel<<<blocks, threads>>>(x, nbr, mask, out, batch);
}

// round 4
// speedup vs baseline: 1.4344x; 1.4344x over previous
#include <cuda_runtime.h>

// PotEnergy1P: out[b] = sum_{i<12,k} exp(-r)/(r+0.01), r = |x[b,i]-nbr[i,k]|
// 2 MUFU per pair (sqrt, ex2); rcp via bit-seed + 2 Newton on FMA pipe;
// all FMA math packed f32x2.
// TLP: 4 warps cover the same 32 batch elems with disjoint site ranges
// (warp-uniform split -> geometry LDS stays a conflict-free broadcast).

#define NSITES 12
#define NMAX   64
#define NGRP   32          // 2-neighbor groups per site

typedef unsigned long long u64;

#define C_NEGL2E 0xBFB8AA3BBFB8AA3BULL   // -log2(e)
#define C_B      0x3C23D70A3C23D70AULL   // 0.01f
#define C_TWO    0x4000000040000000ULL   // 2.0f
#define C_SGN    0x8000000080000000ULL

__device__ __forceinline__ u64 pk2(float lo, float hi) {
    u64 r; asm("mov.b64 %0, {%1,%2};" : "=l"(r) : "f"(lo), "f"(hi)); return r;
}
__device__ __forceinline__ void upk2(float& lo, float& hi, u64 v) {
    asm("mov.b64 {%0,%1}, %2;" : "=f"(lo), "=f"(hi) : "l"(v));
}
__device__ __forceinline__ u64 addx2(u64 a, u64 b) {
    u64 d; asm("add.rn.f32x2 %0,%1,%2;" : "=l"(d) : "l"(a), "l"(b)); return d;
}
__device__ __forceinline__ u64 mulx2(u64 a, u64 b) {
    u64 d; asm("mul.rn.f32x2 %0,%1,%2;" : "=l"(d) : "l"(a), "l"(b)); return d;
}
__device__ __forceinline__ u64 fmax2(u64 a, u64 b, u64 c) {
    u64 d; asm("fma.rn.f32x2 %0,%1,%2,%3;" : "=l"(d) : "l"(a), "l"(b), "l"(c)); return d;
}
__device__ __forceinline__ float fsqrt_approx(float a) {
    float r; asm("sqrt.approx.f32 %0, %1;" : "=f"(r) : "f"(a)); return r;
}
__device__ __forceinline__ float fex2_approx(float a) {
    float r; asm("ex2.approx.f32 %0, %1;" : "=f"(r) : "f"(a)); return r;
}
__device__ __forceinline__ float rcp_seed(float a) {
    return __int_as_float(0x7EF311C3 - __float_as_int(a));
}
__device__ __forceinline__ u64 pkbits(float lo, float hi) {
    return (u64)__float_as_uint(lo) | ((u64)__float_as_uint(hi) << 32);
}

__global__ __launch_bounds__(128)
void pot_energy_kernel(const float* __restrict__ x,
                       const float* __restrict__ nbr,
                       const float* __restrict__ mask,
                       float* __restrict__ out,
                       int batch)
{
    // Geometry per 2-neighbor group, pre-negated + pre-packed:
    //   s_geo[j] = { pk(-nx0,-nx1), pk(-ny0,-ny1) }
    __shared__ ulonglong2 s_geo[NSITES * NGRP];
    __shared__ int        s_ng[NSITES];
    __shared__ float      s_part[3][32];

    for (int j = threadIdx.x; j < NSITES * NGRP; j += blockDim.x) {
        int base = j * 4;
        float nx0 = nbr[base + 0], ny0 = nbr[base + 1];
        float nx1 = nbr[base + 2], ny1 = nbr[base + 3];
        ulonglong2 v;
        v.x = pkbits(-nx0, -nx1);
        v.y = pkbits(-ny0, -ny1);
        s_geo[j] = v;
    }
    if (threadIdx.x < NSITES) {
        int c = 0;
        for (int k = 0; k < NMAX; ++k)
            c += (mask[threadIdx.x * NMAX + k] > 0.5f) ? 1 : 0;
        s_ng[threadIdx.x] = (c + 1) >> 1;       // odd tail self-masks (FAR)
    }
    __syncthreads();

    const int w    = threadIdx.x >> 5;          // warp 0..3 -> sites 3w..3w+2
    const int lane = threadIdx.x & 31;
    const int b    = blockIdx.x * 32 + lane;    // batch element (grid exact)

    // 6 floats: coords of this warp's 3 sites for batch elem b.
    const float* xp = x + (size_t)b * 24 + w * 6;
    float xs[6];
#pragma unroll
    for (int j = 0; j < 3; ++j) {
        float2 v = reinterpret_cast<const float2*>(xp)[j];
        xs[2 * j] = v.x; xs[2 * j + 1] = v.y;
    }

    u64 acc = 0ULL;

#pragma unroll
    for (int s = 0; s < 3; ++s) {
        int site = 3 * w + s;                   // warp-uniform
        u64 xip = pk2(xs[2 * s],     xs[2 * s]);
        u64 yip = pk2(xs[2 * s + 1], xs[2 * s + 1]);
        const ulonglong2* geo = s_geo + site * NGRP;
        int ng = s_ng[site];
#pragma unroll 4
        for (int k = 0; k < ng; ++k) {
            ulonglong2 q = geo[k];              // LDS.128, broadcast (N=1)
            u64 dx = addx2(xip, q.x);           // xi - nx (pre-negated)
            u64 dy = addx2(yip, q.y);
            u64 d2 = fmax2(dx, dx, mulx2(dy, dy));

            float d2l, d2h; upk2(d2l, d2h, d2);
            float rl = fsqrt_approx(d2l);       // MUFU
            float rh = fsqrt_approx(d2h);       // MUFU
            u64 rp = pk2(rl, rh);

            u64 wd   = addx2(rp, C_B);          // r + b
            u64 targ = mulx2(rp, C_NEGL2E);
            float tl, th; upk2(tl, th, targ);
            float el = fex2_approx(tl);         // MUFU (FAR -> 0)
            float eh = fex2_approx(th);         // MUFU
            u64 e = pk2(el, eh);

            float wl, wh; upk2(wl, wh, wd);
            u64 y  = pk2(rcp_seed(wl), rcp_seed(wh));
            u64 wn = wd ^ C_SGN;
            u64 tt = fmax2(wn, y, C_TWO);  y = mulx2(y, tt);
            tt     = fmax2(wn, y, C_TWO);  y = mulx2(y, tt);

            acc = fmax2(e, y, acc);
        }
    }

    float al, ah; upk2(al, ah, acc);
    float v = al + ah;

    if (w > 0) s_part[w - 1][lane] = v;
    __syncthreads();
    if (w == 0) {
        v += s_part[0][lane] + s_part[1][lane] + s_part[2][lane];
        out[b] = v;
    }
}

extern "C" void kernel_launch(void* const* d_in, const int* in_sizes, int n_in,
                              void* d_out, int out_size)
{
    const float* x    = (const float*)d_in[0];   // [B, 24]
    const float* nbr  = (const float*)d_in[1];   // [12, 64, 2]
    const float* mask = (const float*)d_in[2];   // [12, 64]
    float* out        = (float*)d_out;           // [B]

    int batch = in_sizes[0] / 24;                // 131072
    const int threads = 128;                     // 4 warps / 32 batch elems
    int blocks = batch / 32;                     // 4096
    pot_energy_kernel<<<blocks, threads>>>(x, nbr, mask, out, batch);
}

// round 5
// speedup vs baseline: 1.4896x; 1.0385x over previous
#include <cuda_runtime.h>

// PotEnergy1P: out[b] = sum_{i<12,k} exp(-r)/(r+0.01), r = |x[b,i]-nbr[i,k]|
// 2 MUFU per pair (sqrt, ex2) = the floor; rcp via negative-magic bit seed +
// 2 Newton steps on the FMA pipe; all FMA math packed f32x2.
// Geometry pre-scaled by log2(e) so sqrt output feeds ex2 directly (neg folded
// into MUFU operand). Block=256 (8 warps) for 100% occupancy; warp-uniform
// site split keeps geometry LDS a conflict-free broadcast.

#define NSITES 12
#define NMAX   64
#define NGRP   32          // 2-neighbor groups per site

typedef unsigned long long u64;

#define C_NEGLN2 0xBF317218BF317218ULL   // -ln(2)  (s*ln2 = r)
#define C_NEGB   0xBC23D70ABC23D70AULL   // -0.01f
#define C_TWO    0x4000000040000000ULL   //  2.0f
#define C_NEG2   0xC0000000C0000000ULL   // -2.0f

__device__ __forceinline__ u64 pk2(float lo, float hi) {
    u64 r; asm("mov.b64 %0, {%1,%2};" : "=l"(r) : "f"(lo), "f"(hi)); return r;
}
__device__ __forceinline__ void upk2(float& lo, float& hi, u64 v) {
    asm("mov.b64 {%0,%1}, %2;" : "=f"(lo), "=f"(hi) : "l"(v));
}
__device__ __forceinline__ u64 addx2(u64 a, u64 b) {
    u64 d; asm("add.rn.f32x2 %0,%1,%2;" : "=l"(d) : "l"(a), "l"(b)); return d;
}
__device__ __forceinline__ u64 mulx2(u64 a, u64 b) {
    u64 d; asm("mul.rn.f32x2 %0,%1,%2;" : "=l"(d) : "l"(a), "l"(b)); return d;
}
__device__ __forceinline__ u64 fmax2(u64 a, u64 b, u64 c) {
    u64 d; asm("fma.rn.f32x2 %0,%1,%2,%3;" : "=l"(d) : "l"(a), "l"(b), "l"(c)); return d;
}
__device__ __forceinline__ float fsqrt_approx(float a) {
    float r; asm("sqrt.approx.f32 %0, %1;" : "=f"(r) : "f"(a)); return r;
}
// ex2(-a): negation folds into the MUFU source modifier at SASS level.
__device__ __forceinline__ float fex2n(float a) {
    float r;
    asm("{.reg .f32 t; neg.f32 t, %1; ex2.approx.f32 %0, t;}"
        : "=f"(r) : "f"(a));
    return r;
}
// seed for -1/w given wn = -w (wn < 0): same magic, u32 wraparound.
__device__ __forceinline__ float nseed(float a) {
    return __uint_as_float(0x7EF311C3u - __float_as_uint(a));
}
__device__ __forceinline__ u64 pkbits(float lo, float hi) {
    return (u64)__float_as_uint(lo) | ((u64)__float_as_uint(hi) << 32);
}

#define L2E 1.4426950408889634f

__global__ __launch_bounds__(256, 8)
void pot_energy_kernel(const float* __restrict__ x,
                       const float* __restrict__ nbr,
                       const float* __restrict__ mask,
                       float* __restrict__ out,
                       int batch)
{
    // Geometry per 2-neighbor group, pre-negated and pre-scaled by log2(e):
    //   s_geo[j] = { pk(-nx0*L2E, -nx1*L2E), pk(-ny0*L2E, -ny1*L2E) }
    __shared__ ulonglong2 s_geo[NSITES * NGRP];
    __shared__ int        s_ng[NSITES];
    __shared__ float      s_part[3][64];

    for (int j = threadIdx.x; j < NSITES * NGRP; j += blockDim.x) {
        int base = j * 4;
        float nx0 = nbr[base + 0], ny0 = nbr[base + 1];
        float nx1 = nbr[base + 2], ny1 = nbr[base + 3];
        ulonglong2 v;
        v.x = pkbits(-nx0 * L2E, -nx1 * L2E);
        v.y = pkbits(-ny0 * L2E, -ny1 * L2E);
        s_geo[j] = v;
    }
    if (threadIdx.x < NSITES) {
        int c = 0;
        for (int k = 0; k < NMAX; ++k)
            c += (mask[threadIdx.x * NMAX + k] > 0.5f) ? 1 : 0;
        s_ng[threadIdx.x] = (c + 1) >> 1;       // odd tail self-masks (FAR)
    }
    __syncthreads();

    const int w    = threadIdx.x >> 5;          // 0..7
    const int half = w >> 2;                    // 0/1: batch sub-chunk
    const int sw   = w & 3;                     // site group -> sites 3sw..3sw+2
    const int lane = threadIdx.x & 31;
    const int hb   = half * 32 + lane;          // 0..63 within block
    const int b    = blockIdx.x * 64 + hb;      // batch element (grid exact)

    // coords of this warp's 3 sites, pre-scaled by log2(e)
    const float* xp = x + (size_t)b * 24 + sw * 6;
    float xs[6];
#pragma unroll
    for (int j = 0; j < 3; ++j) {
        float2 v = reinterpret_cast<const float2*>(xp)[j];
        xs[2 * j] = v.x * L2E; xs[2 * j + 1] = v.y * L2E;
    }

    u64 acc = 0ULL;

#pragma unroll
    for (int s = 0; s < 3; ++s) {
        int site = 3 * sw + s;                  // warp-uniform
        u64 xip = pk2(xs[2 * s],     xs[2 * s]);
        u64 yip = pk2(xs[2 * s + 1], xs[2 * s + 1]);
        const ulonglong2* geo = s_geo + site * NGRP;
        int ng = s_ng[site];
#pragma unroll 4
        for (int k = 0; k < ng; ++k) {
            ulonglong2 q = geo[k];              // LDS.128, broadcast
            u64 dx = addx2(xip, q.x);           // (xi-nx)*L2E
            u64 dy = addx2(yip, q.y);
            u64 d2 = fmax2(dx, dx, mulx2(dy, dy));

            float d2l, d2h; upk2(d2l, d2h, d2);
            float sl = fsqrt_approx(d2l);       // MUFU: s = r*log2(e)
            float sh = fsqrt_approx(d2h);       // MUFU
            float el = fex2n(sl);               // MUFU: exp(-r) (FAR -> 0)
            float eh = fex2n(sh);               // MUFU
            u64 sp = pk2(sl, sh);
            u64 ep = pk2(el, eh);

            u64 wn = fmax2(sp, C_NEGLN2, C_NEGB);   // -(r+b)
            float wnl, wnh; upk2(wnl, wnh, wn);
            u64 yn = pk2(nseed(wnl), nseed(wnh));   // ~ -(1/w)
            u64 t1 = fmax2(wn, yn, C_NEG2);         // w*y - 2
            u64 y1 = mulx2(yn, t1);                 // y(2-wy) > 0
            u64 t2 = fmax2(wn, y1, C_TWO);          // 2 - w*y1
            u64 y2 = mulx2(y1, t2);                 // 1/w
            acc = fmax2(ep, y2, acc);               // += exp(-r)/(r+b)
        }
    }

    float al, ah; upk2(al, ah, acc);
    float v = al + ah;

    if (sw > 0) s_part[sw - 1][hb] = v;
    __syncthreads();
    if (sw == 0) {
        v += s_part[0][hb] + s_part[1][hb] + s_part[2][hb];
        out[b] = v;
    }
}

extern "C" void kernel_launch(void* const* d_in, const int* in_sizes, int n_in,
                              void* d_out, int out_size)
{
    const float* x    = (const float*)d_in[0];   // [B, 24]
    const float* nbr  = (const float*)d_in[1];   // [12, 64, 2]
    const float* mask = (const float*)d_in[2];   // [12, 64]
    float* out        = (float*)d_out;           // [B]

    int batch = in_sizes[0] / 24;                // 131072
    const int threads = 256;                     // 8 warps / 64 batch elems
    int blocks = batch / 64;                     // 2048
    pot_energy_kernel<<<blocks, threads>>>(x, nbr, mask, out, batch);
}